// round 15
// baseline (speedup 1.0000x reference)
#include <cuda_runtime.h>
#include <cuda_bf16.h>

typedef unsigned long long ull;

// ---------------- problem constants ----------------
#define NN    65536
#define HIDD  256
#define BB    64
#define EPER  8192
#define ET    524288
#define NRES  4096
#define EC    262144

// ---------------- output offsets (float32 elements) ----------------
#define OFF_CX   0ul
#define OFF_CEI  16777216ul
#define OFF_CW   17301504ul
#define OFF_CB   17563648ul
#define OFF_FX   17629184ul
#define OFF_FEI  34406400ul
#define OFF_FW   34930688ul
#define OFF_FB   35192832ul
#define OFF_ES   35258368ul

// ---------------- scratch (zero-initialized at module load) ----------------
__device__ float g_t[NN * HIDD];
__device__ float g_u[NN * HIDD];
__device__ float g_h[NN * HIDD];
__device__ int   g_deg[NN + 1];   // 0 at entry; re-zeroed at tail
__device__ int   g_pos[NN];
__device__ int   g_col[ET];
__device__ float g_ssrc[NN];
__device__ float g_sdst[NN];
__device__ int   g_cei[2 * EC];
__device__ int   g_fei[2 * EC];
__device__ int   g_pres_c[NN];    // 0 at entry; re-zeroed at tail
__device__ int   g_pres_f[NN];
__device__ int   g_rank_c[NN];
__device__ int   g_rank_f[NN];
__device__ int   g_list_c[NN];
__device__ int   g_list_f[NN];
__device__ int   g_cnt_c;
__device__ int   g_cnt_f;

// ---------------- f32x2 FFMA2 helpers ----------------
__device__ __forceinline__ void fma2(ull& d, ull a, ull b) {
    asm("fma.rn.f32x2 %0, %1, %2, %0;" : "+l"(d) : "l"(a), "l"(b));
}
__device__ __forceinline__ ull dup2(float x) {
    ull r;
    asm("mov.b64 %0, {%1, %1};" : "=l"(r) : "r"(__float_as_uint(x)));
    return r;
}

// ---------------- CSR build ----------------
__global__ void k_count_deg(const int* __restrict__ ei) {
    int e = blockIdx.x * blockDim.x + threadIdx.x;
    if (e < ET) atomicAdd(&g_deg[ei[e] + 1], 1);
}

__global__ __launch_bounds__(1024) void k_scan_deg() {
    __shared__ int part[1024];
    const int t = threadIdx.x;
    const int CH = 65;
    int base = t * CH;
    int n = 0;
    if (base < NN + 1) { n = NN + 1 - base; if (n > CH) n = CH; }
    int s = 0;
    for (int i = 0; i < n; i++) s += g_deg[base + i];
    part[t] = s;
    __syncthreads();
    for (int off = 1; off < 1024; off <<= 1) {
        int v = (t >= off) ? part[t - off] : 0;
        __syncthreads();
        part[t] += v;
        __syncthreads();
    }
    int run = part[t] - s;
    for (int i = 0; i < n; i++) {
        run += g_deg[base + i];
        g_deg[base + i] = run;
        if (base + i < NN) g_pos[base + i] = run;
    }
}

__global__ void k_fill_csr(const int* __restrict__ ei) {
    int e = blockIdx.x * blockDim.x + threadIdx.x;
    if (e < ET) {
        int r = ei[e];
        int p = atomicAdd(&g_pos[r], 1);
        g_col[p] = ei[ET + e];
    }
}

// ---------------- aggregation: block = 2 nodes, 64 lanes/node ----------------
__global__ __launch_bounds__(128) void k_agg(const float* __restrict__ hin,
                                             float* __restrict__ tout) {
    int v = blockIdx.x * 2 + (threadIdx.x >> 6);
    int lane = threadIdx.x & 63;
    const float4* H = (const float4*)hin;
    float4 acc = H[(size_t)v * 64 + lane];
    int s = g_deg[v], e = g_deg[v + 1];
    int i = s;
    for (; i + 4 <= e; i += 4) {
        int n0 = g_col[i], n1 = g_col[i + 1], n2 = g_col[i + 2], n3 = g_col[i + 3];
        float4 x0 = H[(size_t)n0 * 64 + lane];
        float4 x1 = H[(size_t)n1 * 64 + lane];
        float4 x2 = H[(size_t)n2 * 64 + lane];
        float4 x3 = H[(size_t)n3 * 64 + lane];
        acc.x += x0.x + x1.x + x2.x + x3.x;
        acc.y += x0.y + x1.y + x2.y + x3.y;
        acc.z += x0.z + x1.z + x2.z + x3.z;
        acc.w += x0.w + x1.w + x2.w + x3.w;
    }
    for (; i < e; i++) {
        int nb = g_col[i];
        float4 x = H[(size_t)nb * 64 + lane];
        acc.x += x.x; acc.y += x.y; acc.z += x.z; acc.w += x.w;
    }
    ((float4*)tout)[(size_t)v * 64 + lane] = acc;
}

// ---------------- GEMM: C = relu(A @ W + bias) ----------------
// Occupancy push: 128x64 block tile, 8x4 micro-tile, 16-ull accumulators
// (~75 regs) -> 3 CTAs/SM = 24 warps. Plain transposed A (no dup), FFMA2.
#define BM 128
#define BN 64
#define BK 16
#define AS_W 132   // 128 + 4 pad

__global__ __launch_bounds__(256, 3) void k_gemm_bias_relu(const float* __restrict__ A,
                                                           const float* __restrict__ W,
                                                           const float* __restrict__ bias,
                                                           float* __restrict__ C) {
    __shared__ float As[BK][AS_W];   // As[k][m] = A[m][k]
    __shared__ float Bs[BK][BN];     // Bs[k][n]

    const int bm = blockIdx.x;
    const int bn = blockIdx.y;
    const int t  = threadIdx.x;
    const int tx = t & 15;    // 16 col groups of 4
    const int ty = t >> 4;    // 16 row groups of (4+4)

    const int a_row0 = t >> 2,          a_kk0 = (t & 3) * 4;
    const int a_row1 = a_row0 + 64;
    const int b_r = t >> 4,             b_c = (t & 15) * 4;   // 16x64: 1 float4/thread

    const float* Ab = A + (size_t)(bm * BM) * 256;
    const float* Wb = W + bn * BN;

    ull acc[8][2];
#pragma unroll
    for (int m = 0; m < 8; m++) { acc[m][0] = 0ull; acc[m][1] = 0ull; }

    float4 ra0 = *(const float4*)&Ab[(size_t)a_row0 * 256 + a_kk0];
    float4 ra1 = *(const float4*)&Ab[(size_t)a_row1 * 256 + a_kk0];
    float4 rb  = *(const float4*)&Wb[(size_t)b_r * 256 + b_c];

    for (int k0 = 0; k0 < 256; k0 += BK) {
        As[a_kk0 + 0][a_row0] = ra0.x;
        As[a_kk0 + 1][a_row0] = ra0.y;
        As[a_kk0 + 2][a_row0] = ra0.z;
        As[a_kk0 + 3][a_row0] = ra0.w;
        As[a_kk0 + 0][a_row1] = ra1.x;
        As[a_kk0 + 1][a_row1] = ra1.y;
        As[a_kk0 + 2][a_row1] = ra1.z;
        As[a_kk0 + 3][a_row1] = ra1.w;
        *(float4*)&Bs[b_r][b_c] = rb;
        __syncthreads();

        if (k0 + BK < 256) {
            int kn = k0 + BK;
            ra0 = *(const float4*)&Ab[(size_t)a_row0 * 256 + kn + a_kk0];
            ra1 = *(const float4*)&Ab[(size_t)a_row1 * 256 + kn + a_kk0];
            rb  = *(const float4*)&Wb[(size_t)(kn + b_r) * 256 + b_c];
        }

#pragma unroll
        for (int k = 0; k < BK; k++) {
            float4 a0 = *(const float4*)&As[k][ty * 4];          // rows 4ty..4ty+3
            float4 a1 = *(const float4*)&As[k][64 + ty * 4];     // rows 64+4ty..
            ulonglong2 B0 = *(const ulonglong2*)&Bs[k][4 * tx];  // cols 4tx..4tx+3
            {
                ull av = dup2(a0.x);
                fma2(acc[0][0], av, B0.x); fma2(acc[0][1], av, B0.y);
            }
            {
                ull av = dup2(a0.y);
                fma2(acc[1][0], av, B0.x); fma2(acc[1][1], av, B0.y);
            }
            {
                ull av = dup2(a0.z);
                fma2(acc[2][0], av, B0.x); fma2(acc[2][1], av, B0.y);
            }
            {
                ull av = dup2(a0.w);
                fma2(acc[3][0], av, B0.x); fma2(acc[3][1], av, B0.y);
            }
            {
                ull av = dup2(a1.x);
                fma2(acc[4][0], av, B0.x); fma2(acc[4][1], av, B0.y);
            }
            {
                ull av = dup2(a1.y);
                fma2(acc[5][0], av, B0.x); fma2(acc[5][1], av, B0.y);
            }
            {
                ull av = dup2(a1.z);
                fma2(acc[6][0], av, B0.x); fma2(acc[6][1], av, B0.y);
            }
            {
                ull av = dup2(a1.w);
                fma2(acc[7][0], av, B0.x); fma2(acc[7][1], av, B0.y);
            }
        }
        __syncthreads();
    }

    float4 bv = *(const float4*)&bias[bn * BN + tx * 4];
#pragma unroll
    for (int m = 0; m < 8; m++) {
        int row = bm * BM + ((m < 4) ? (ty * 4 + m) : (64 + ty * 4 + m - 4));
        float2 p0 = *(float2*)&acc[m][0];
        float2 p1 = *(float2*)&acc[m][1];
        float4 r;
        r.x = fmaxf(p0.x + bv.x, 0.f);
        r.y = fmaxf(p0.y + bv.y, 0.f);
        r.z = fmaxf(p1.x + bv.z, 0.f);
        r.w = fmaxf(p1.y + bv.w, 0.f);
        *(float4*)&C[(size_t)row * 256 + bn * BN + tx * 4] = r;
    }
}

// ---------------- scores ----------------
__global__ __launch_bounds__(256) void k_score(const float* __restrict__ h,
                                               const float* __restrict__ wsc) {
    int gw = (blockIdx.x * blockDim.x + threadIdx.x) >> 5;
    int lane = threadIdx.x & 31;
    if (gw >= NN) return;
    const float4* H = (const float4*)(h + (size_t)gw * 256);
    const float4* W1 = (const float4*)wsc;
    const float4* W2 = (const float4*)(wsc + 256);
    float s1 = 0.f, s2 = 0.f;
#pragma unroll
    for (int i = lane; i < 64; i += 32) {
        float4 hv = H[i], w1 = W1[i], w2 = W2[i];
        s1 += hv.x * w1.x + hv.y * w1.y + hv.z * w1.z + hv.w * w1.w;
        s2 += hv.x * w2.x + hv.y * w2.y + hv.z * w2.z + hv.w * w2.w;
    }
#pragma unroll
    for (int o = 16; o; o >>= 1) {
        s1 += __shfl_xor_sync(0xffffffffu, s1, o);
        s2 += __shfl_xor_sync(0xffffffffu, s2, o);
    }
    if (lane == 0) { g_ssrc[gw] = s1; g_sdst[gw] = s2; }
}

__global__ void k_edge_score(const int* __restrict__ ei,
                             const float* __restrict__ bsc,
                             float* __restrict__ out) {
    int e = blockIdx.x * blockDim.x + threadIdx.x;
    if (e < ET) {
        out[OFF_ES + e] = g_ssrc[ei[e]] + g_sdst[ei[ET + e]] + bsc[0];
    }
}

// ---------------- sort emit ----------------
__device__ __forceinline__ void sort_emit(int b, int idx_i, int i,
                                          const float* es, const int* ei,
                                          float* out) {
    int ge = b * EPER + idx_i;
    float s = es[ge];
    int r = ei[ge];
    int c = ei[ET + ge];
    if (i < NRES) {
        int p = b * NRES + i;
        out[OFF_CW + p] = s;
        g_cei[p] = r; g_cei[EC + p] = c;
        g_pres_c[r] = 1; g_pres_c[c] = 1;
    } else {
        int p = b * NRES + (i - NRES);
        out[OFF_FW + p] = -s;
        g_fei[p] = r; g_fei[EC + p] = c;
        g_pres_f[r] = 1; g_pres_f[c] = 1;
    }
}

// ---------------- sort: u64 packed keys, 64KB dynamic smem (measured 87us) ----------------
__global__ __launch_bounds__(1024) void k_sort64(const float* __restrict__ es,
                                                 const int* __restrict__ ei,
                                                 float* __restrict__ out) {
    extern __shared__ ull key[];
    const int b = blockIdx.x;
    const int tid = threadIdx.x;

    for (int i = tid; i < EPER; i += 1024) {
        unsigned u = __float_as_uint(es[b * EPER + i]);
        u = (u & 0x80000000u) ? ~u : (u | 0x80000000u);
        key[i] = ((ull)(~u) << 16) | (unsigned)i;
    }
    __syncthreads();

    for (int k = 2; k <= EPER; k <<= 1) {
        for (int j = k >> 1; j > 0; j >>= 1) {
#pragma unroll
            for (int q = 0; q < 4; q++) {
                int p = tid + q * 1024;
                int i = ((p & ~(j - 1)) << 1) | (p & (j - 1));
                int l = i | j;
                bool up = ((i & k) == 0);
                ull a = key[i], c = key[l];
                if ((a > c) == up) { key[i] = c; key[l] = a; }
            }
            __syncthreads();
        }
    }

    for (int i = tid; i < EPER; i += 1024) {
        int idx = (int)(key[i] & 0xFFFFu);
        sort_emit(b, idx, i, es, ei, out);
    }
}

// ---------------- FALLBACK sort: static 48KB (proven) ----------------
__global__ __launch_bounds__(1024) void k_sort_static(const float* __restrict__ es,
                                                      const int* __restrict__ ei,
                                                      float* __restrict__ out) {
    __shared__ unsigned int   kh[EPER];
    __shared__ unsigned short kl[EPER];
    const int b = blockIdx.x;
    const int tid = threadIdx.x;

    for (int i = tid; i < EPER; i += 1024) {
        unsigned u = __float_as_uint(es[b * EPER + i]);
        u = (u & 0x80000000u) ? ~u : (u | 0x80000000u);
        kh[i] = ~u;
        kl[i] = (unsigned short)i;
    }
    __syncthreads();

    for (int k = 2; k <= EPER; k <<= 1) {
        for (int j = k >> 1; j > 0; j >>= 1) {
#pragma unroll
            for (int q = 0; q < 4; q++) {
                int p = tid + q * 1024;
                int i = ((p & ~(j - 1)) << 1) | (p & (j - 1));
                int l = i | j;
                bool up = ((i & k) == 0);
                unsigned ah = kh[i], bh = kh[l];
                unsigned short al = kl[i], bl = kl[l];
                bool agtb = (ah > bh) || (ah == bh && al > bl);
                if (agtb == up) {
                    kh[i] = bh; kh[l] = ah;
                    kl[i] = bl; kl[l] = al;
                }
            }
            __syncthreads();
        }
    }

    for (int i = tid; i < EPER; i += 1024) {
        int idx = kl[i];
        sort_emit(b, idx, i, es, ei, out);
    }
}

// ---------------- relabel: compact + batch fill ----------------
__global__ __launch_bounds__(1024) void k_compact(const int* __restrict__ batch_in,
                                                  float* __restrict__ out) {
    __shared__ int part[1024];
    const int which = blockIdx.x;
    const int* pres = which ? g_pres_f : g_pres_c;
    int* rank = which ? g_rank_f : g_rank_c;
    int* list = which ? g_list_f : g_list_c;
    int* cnt = which ? &g_cnt_f : &g_cnt_c;
    float* out_b = out + (which ? OFF_FB : OFF_CB);

    const int t = threadIdx.x;
    const int base = t * 64;
    int s = 0;
    for (int i = 0; i < 64; i++) s += pres[base + i];
    part[t] = s;
    __syncthreads();
    for (int off = 1; off < 1024; off <<= 1) {
        int v = (t >= off) ? part[t - off] : 0;
        __syncthreads();
        part[t] += v;
        __syncthreads();
    }
    int total = part[1023];
    int run = part[t] - s;
    for (int i = 0; i < 64; i++) {
        int v = base + i;
        if (pres[v]) {
            rank[v] = run;
            list[run] = v;
            out_b[run] = (float)batch_in[v];
            run++;
        }
    }
    for (int i = 0; i < 64; i++) {
        int p = base + i;
        if (p >= total) out_b[p] = -1.0f;
    }
    if (t == 1023) *cnt = total;
}

// ---------------- fused emit: gather_x (bx < GX_BLK) + ei_rel (rest) ----------------
#define GX_BLK 16384   // NN*64/256
#define EIR_BLK 2048   // 2*EC/256

__global__ void k_emit(const float* __restrict__ h, float* __restrict__ out) {
    const int which = blockIdx.y;
    const int bx = blockIdx.x;
    if (bx < GX_BLK) {
        int gid = bx * 256 + threadIdx.x;
        int row = gid >> 6;
        int c = gid & 63;
        int cnt = which ? g_cnt_f : g_cnt_c;
        float4 v;
        if (row < cnt) {
            int src = which ? g_list_f[row] : g_list_c[row];
            v = ((const float4*)h)[(size_t)src * 64 + c];
        } else {
            v = make_float4(0.f, 0.f, 0.f, 0.f);
        }
        float* outx = out + (which ? OFF_FX : OFF_CX);
        ((float4*)outx)[gid] = v;
    } else {
        int k = (bx - GX_BLK) * 256 + threadIdx.x;
        const int* eib = which ? g_fei : g_cei;
        const int* rank = which ? g_rank_f : g_rank_c;
        float* dst = out + (which ? OFF_FEI : OFF_CEI);
        dst[k] = (float)rank[eib[k]];
    }
}

// tail: restore zero-state invariant for next graph replay
__global__ void k_rezero() {
    int i = blockIdx.x * blockDim.x + threadIdx.x;
    if (i <= NN) g_deg[i] = 0;
    if (i < NN) { g_pres_c[i] = 0; g_pres_f[i] = 0; }
}

// ---------------- launch ----------------
extern "C" void kernel_launch(void* const* d_in, const int* in_sizes, int n_in,
                              void* d_out, int out_size) {
    (void)in_sizes; (void)n_in; (void)out_size;
    const float* x    = (const float*)d_in[0];
    const int*   ei   = (const int*)d_in[1];
    const int*   batch= (const int*)d_in[2];
    const float* W11  = (const float*)d_in[3];
    const float* b11  = (const float*)d_in[4];
    const float* W12  = (const float*)d_in[5];
    const float* b12  = (const float*)d_in[6];
    const float* W21  = (const float*)d_in[7];
    const float* b21  = (const float*)d_in[8];
    const float* W22  = (const float*)d_in[9];
    const float* b22  = (const float*)d_in[10];
    const float* wsc  = (const float*)d_in[11];
    const float* bsc  = (const float*)d_in[12];
    float* out = (float*)d_out;

    const int SMEM_SORT = EPER * (int)sizeof(ull);   // 65536
    bool use64 = (cudaFuncSetAttribute(k_sort64,
                    cudaFuncAttributeMaxDynamicSharedMemorySize,
                    SMEM_SORT) == cudaSuccess);

    dim3 ggrid(NN / BM, HIDD / BN);   // (512, 4)

    k_count_deg<<<ET / 256, 256>>>(ei);                      // 0
    k_scan_deg<<<1, 1024>>>();                               // 1
    k_fill_csr<<<ET / 256, 256>>>(ei);                       // 2

    k_agg<<<NN / 2, 128>>>(x, g_t);                          // 3
    k_gemm_bias_relu<<<ggrid, 256>>>(g_t, W11, b11, g_u);    // 4
    k_gemm_bias_relu<<<ggrid, 256>>>(g_u, W12, b12, g_h);    // 5

    k_agg<<<NN / 2, 128>>>(g_h, g_t);                        // 6
    k_gemm_bias_relu<<<ggrid, 256>>>(g_t, W21, b21, g_u);    // 7
    k_gemm_bias_relu<<<ggrid, 256>>>(g_u, W22, b22, g_h);    // 8

    k_score<<<(NN * 32) / 256, 256>>>(g_h, wsc);             // 9
    k_edge_score<<<ET / 256, 256>>>(ei, bsc, out);           // 10

    if (use64) {
        k_sort64<<<BB, 1024, SMEM_SORT>>>(out + OFF_ES, ei, out);   // 11
    } else {
        k_sort_static<<<BB, 1024>>>(out + OFF_ES, ei, out);         // 11
    }

    k_compact<<<2, 1024>>>(batch, out);                      // 12
    k_emit<<<dim3(GX_BLK + EIR_BLK, 2), 256>>>(g_h, out);    // 13

    k_rezero<<<(NN + 256) / 256, 256>>>();                   // 14
}

// round 16
// speedup vs baseline: 1.3743x; 1.3743x over previous
#include <cuda_runtime.h>
#include <cuda_bf16.h>

typedef unsigned long long ull;

// ---------------- problem constants ----------------
#define NN    65536
#define HIDD  256
#define BB    64
#define EPER  8192
#define ET    524288
#define NRES  4096
#define EC    262144

// ---------------- output offsets (float32 elements) ----------------
#define OFF_CX   0ul
#define OFF_CEI  16777216ul
#define OFF_CW   17301504ul
#define OFF_CB   17563648ul
#define OFF_FX   17629184ul
#define OFF_FEI  34406400ul
#define OFF_FW   34930688ul
#define OFF_FB   35192832ul
#define OFF_ES   35258368ul

// ---------------- scratch (zero-initialized at module load) ----------------
__device__ float g_t[NN * HIDD];
__device__ float g_u[NN * HIDD];
__device__ float g_h[NN * HIDD];
__device__ int   g_deg[NN + 1];   // 0 at entry; re-zeroed at tail
__device__ int   g_pos[NN];
__device__ int   g_col[ET];
__device__ float g_ps[2 * NN];    // partial s_src per bn half
__device__ float g_pd[2 * NN];    // partial s_dst per bn half
__device__ int   g_cei[2 * EC];
__device__ int   g_fei[2 * EC];
__device__ int   g_pres_c[NN];    // 0 at entry; re-zeroed at tail
__device__ int   g_pres_f[NN];
__device__ int   g_rank_c[NN];
__device__ int   g_rank_f[NN];
__device__ int   g_list_c[NN];
__device__ int   g_list_f[NN];
__device__ int   g_cnt_c;
__device__ int   g_cnt_f;

// ---------------- f32x2 FFMA2 helpers ----------------
__device__ __forceinline__ void fma2(ull& d, ull a, ull b) {
    asm("fma.rn.f32x2 %0, %1, %2, %0;" : "+l"(d) : "l"(a), "l"(b));
}
__device__ __forceinline__ ull dup2(float x) {
    ull r;
    asm("mov.b64 %0, {%1, %1};" : "=l"(r) : "r"(__float_as_uint(x)));
    return r;
}

// ---------------- CSR build ----------------
__global__ void k_count_deg(const int* __restrict__ ei) {
    int e = blockIdx.x * blockDim.x + threadIdx.x;
    if (e < ET) atomicAdd(&g_deg[ei[e] + 1], 1);
}

__global__ __launch_bounds__(1024) void k_scan_deg() {
    __shared__ int part[1024];
    const int t = threadIdx.x;
    const int CH = 65;
    int base = t * CH;
    int n = 0;
    if (base < NN + 1) { n = NN + 1 - base; if (n > CH) n = CH; }
    int s = 0;
    for (int i = 0; i < n; i++) s += g_deg[base + i];
    part[t] = s;
    __syncthreads();
    for (int off = 1; off < 1024; off <<= 1) {
        int v = (t >= off) ? part[t - off] : 0;
        __syncthreads();
        part[t] += v;
        __syncthreads();
    }
    int run = part[t] - s;
    for (int i = 0; i < n; i++) {
        run += g_deg[base + i];
        g_deg[base + i] = run;
        if (base + i < NN) g_pos[base + i] = run;
    }
}

__global__ void k_fill_csr(const int* __restrict__ ei) {
    int e = blockIdx.x * blockDim.x + threadIdx.x;
    if (e < ET) {
        int r = ei[e];
        int p = atomicAdd(&g_pos[r], 1);
        g_col[p] = ei[ET + e];
    }
}

// ---------------- aggregation: block = 2 nodes, 64 lanes/node ----------------
__global__ __launch_bounds__(128) void k_agg(const float* __restrict__ hin,
                                             float* __restrict__ tout) {
    int v = blockIdx.x * 2 + (threadIdx.x >> 6);
    int lane = threadIdx.x & 63;
    const float4* H = (const float4*)hin;
    float4 acc = H[(size_t)v * 64 + lane];
    int s = g_deg[v], e = g_deg[v + 1];
    int i = s;
    for (; i + 4 <= e; i += 4) {
        int n0 = g_col[i], n1 = g_col[i + 1], n2 = g_col[i + 2], n3 = g_col[i + 3];
        float4 x0 = H[(size_t)n0 * 64 + lane];
        float4 x1 = H[(size_t)n1 * 64 + lane];
        float4 x2 = H[(size_t)n2 * 64 + lane];
        float4 x3 = H[(size_t)n3 * 64 + lane];
        acc.x += x0.x + x1.x + x2.x + x3.x;
        acc.y += x0.y + x1.y + x2.y + x3.y;
        acc.z += x0.z + x1.z + x2.z + x3.z;
        acc.w += x0.w + x1.w + x2.w + x3.w;
    }
    for (; i < e; i++) {
        int nb = g_col[i];
        float4 x = H[(size_t)nb * 64 + lane];
        acc.x += x.x; acc.y += x.y; acc.z += x.z; acc.w += x.w;
    }
    ((float4*)tout)[(size_t)v * 64 + lane] = acc;
}

// ---------------- GEMM core macros (R14 proven config) ----------------
#define BM 128
#define BN 128
#define BK 16
#define AS_W 132   // 128 + 4 pad

#define GEMM_PROLOG_AND_LOOP                                                  \
    __shared__ float As[BK][AS_W];                                            \
    __shared__ float Bs[BK][BN];                                              \
    const int bm = blockIdx.x;                                                \
    const int bn = blockIdx.y;                                                \
    const int t  = threadIdx.x;                                               \
    const int tx = t & 15;                                                    \
    const int ty = t >> 4;                                                    \
    const int a_row0 = t >> 2,          a_kk0 = (t & 3) * 4;                  \
    const int a_row1 = a_row0 + 64;                                           \
    const int b_r0 = t >> 5,            b_c0 = (t & 31) * 4;                  \
    const int b_r1 = b_r0 + 8;                                                \
    const float* Ab = A + (size_t)(bm * BM) * 256;                            \
    const float* Wb = W + bn * BN;                                            \
    ull acc[8][4];                                                            \
    _Pragma("unroll")                                                         \
    for (int m = 0; m < 8; m++)                                               \
        _Pragma("unroll")                                                     \
        for (int n = 0; n < 4; n++) acc[m][n] = 0ull;                         \
    float4 ra0 = *(const float4*)&Ab[(size_t)a_row0 * 256 + a_kk0];           \
    float4 ra1 = *(const float4*)&Ab[(size_t)a_row1 * 256 + a_kk0];           \
    float4 rb0 = *(const float4*)&Wb[(size_t)b_r0 * 256 + b_c0];              \
    float4 rb1 = *(const float4*)&Wb[(size_t)b_r1 * 256 + b_c0];              \
    for (int k0 = 0; k0 < 256; k0 += BK) {                                    \
        As[a_kk0 + 0][a_row0] = ra0.x;                                        \
        As[a_kk0 + 1][a_row0] = ra0.y;                                        \
        As[a_kk0 + 2][a_row0] = ra0.z;                                        \
        As[a_kk0 + 3][a_row0] = ra0.w;                                        \
        As[a_kk0 + 0][a_row1] = ra1.x;                                        \
        As[a_kk0 + 1][a_row1] = ra1.y;                                        \
        As[a_kk0 + 2][a_row1] = ra1.z;                                        \
        As[a_kk0 + 3][a_row1] = ra1.w;                                        \
        *(float4*)&Bs[b_r0][b_c0] = rb0;                                      \
        *(float4*)&Bs[b_r1][b_c0] = rb1;                                      \
        __syncthreads();                                                      \
        if (k0 + BK < 256) {                                                  \
            int kn = k0 + BK;                                                 \
            ra0 = *(const float4*)&Ab[(size_t)a_row0 * 256 + kn + a_kk0];     \
            ra1 = *(const float4*)&Ab[(size_t)a_row1 * 256 + kn + a_kk0];     \
            rb0 = *(const float4*)&Wb[(size_t)(kn + b_r0) * 256 + b_c0];      \
            rb1 = *(const float4*)&Wb[(size_t)(kn + b_r1) * 256 + b_c0];      \
        }                                                                     \
        _Pragma("unroll")                                                     \
        for (int k = 0; k < BK; k++) {                                        \
            float4 a0 = *(const float4*)&As[k][ty * 4];                       \
            float4 a1 = *(const float4*)&As[k][64 + ty * 4];                  \
            ulonglong2 B0 = *(const ulonglong2*)&Bs[k][4 * tx];               \
            ulonglong2 B1 = *(const ulonglong2*)&Bs[k][64 + 4 * tx];          \
            { ull av = dup2(a0.x);                                            \
              fma2(acc[0][0], av, B0.x); fma2(acc[0][1], av, B0.y);           \
              fma2(acc[0][2], av, B1.x); fma2(acc[0][3], av, B1.y); }         \
            { ull av = dup2(a0.y);                                            \
              fma2(acc[1][0], av, B0.x); fma2(acc[1][1], av, B0.y);           \
              fma2(acc[1][2], av, B1.x); fma2(acc[1][3], av, B1.y); }         \
            { ull av = dup2(a0.z);                                            \
              fma2(acc[2][0], av, B0.x); fma2(acc[2][1], av, B0.y);           \
              fma2(acc[2][2], av, B1.x); fma2(acc[2][3], av, B1.y); }         \
            { ull av = dup2(a0.w);                                            \
              fma2(acc[3][0], av, B0.x); fma2(acc[3][1], av, B0.y);           \
              fma2(acc[3][2], av, B1.x); fma2(acc[3][3], av, B1.y); }         \
            { ull av = dup2(a1.x);                                            \
              fma2(acc[4][0], av, B0.x); fma2(acc[4][1], av, B0.y);           \
              fma2(acc[4][2], av, B1.x); fma2(acc[4][3], av, B1.y); }         \
            { ull av = dup2(a1.y);                                            \
              fma2(acc[5][0], av, B0.x); fma2(acc[5][1], av, B0.y);           \
              fma2(acc[5][2], av, B1.x); fma2(acc[5][3], av, B1.y); }         \
            { ull av = dup2(a1.z);                                            \
              fma2(acc[6][0], av, B0.x); fma2(acc[6][1], av, B0.y);           \
              fma2(acc[6][2], av, B1.x); fma2(acc[6][3], av, B1.y); }         \
            { ull av = dup2(a1.w);                                            \
              fma2(acc[7][0], av, B0.x); fma2(acc[7][1], av, B0.y);           \
              fma2(acc[7][2], av, B1.x); fma2(acc[7][3], av, B1.y); }         \
        }                                                                     \
        __syncthreads();                                                      \
    }                                                                         \
    float4 bv0 = *(const float4*)&bias[bn * BN + tx * 4];                     \
    float4 bv1 = *(const float4*)&bias[bn * BN + 64 + tx * 4];

// ---------------- GEMM: C = relu(A @ W + bias)  (R14 champion) ----------------
__global__ __launch_bounds__(256, 2) void k_gemm_bias_relu(const float* __restrict__ A,
                                                           const float* __restrict__ W,
                                                           const float* __restrict__ bias,
                                                           float* __restrict__ C) {
    GEMM_PROLOG_AND_LOOP
#pragma unroll
    for (int m = 0; m < 8; m++) {
        int row = bm * BM + ((m < 4) ? (ty * 4 + m) : (64 + ty * 4 + m - 4));
        float2 p0 = *(float2*)&acc[m][0];
        float2 p1 = *(float2*)&acc[m][1];
        float2 p2 = *(float2*)&acc[m][2];
        float2 p3 = *(float2*)&acc[m][3];
        float4 r0, r1;
        r0.x = fmaxf(p0.x + bv0.x, 0.f);
        r0.y = fmaxf(p0.y + bv0.y, 0.f);
        r0.z = fmaxf(p1.x + bv0.z, 0.f);
        r0.w = fmaxf(p1.y + bv0.w, 0.f);
        r1.x = fmaxf(p2.x + bv1.x, 0.f);
        r1.y = fmaxf(p2.y + bv1.y, 0.f);
        r1.z = fmaxf(p3.x + bv1.z, 0.f);
        r1.w = fmaxf(p3.y + bv1.w, 0.f);
        *(float4*)&C[(size_t)row * 256 + bn * BN + tx * 4] = r0;
        *(float4*)&C[(size_t)row * 256 + bn * BN + 64 + tx * 4] = r1;
    }
}

// ---------------- final GEMM clone: also emits per-bn score partials ----------------
// g_ps[bn*NN+row] = dot(h_row[cols of bn], wsc[:256] slice)
// g_pd likewise with wsc[256:]. No atomics; deterministic.
__global__ __launch_bounds__(256, 2) void k_gemm_score(const float* __restrict__ A,
                                                       const float* __restrict__ W,
                                                       const float* __restrict__ bias,
                                                       float* __restrict__ C,
                                                       const float* __restrict__ wsc) {
    GEMM_PROLOG_AND_LOOP
    float4 ws0 = *(const float4*)&wsc[bn * BN + tx * 4];
    float4 ws1 = *(const float4*)&wsc[bn * BN + 64 + tx * 4];
    float4 wd0 = *(const float4*)&wsc[256 + bn * BN + tx * 4];
    float4 wd1 = *(const float4*)&wsc[256 + bn * BN + 64 + tx * 4];
#pragma unroll
    for (int m = 0; m < 8; m++) {
        int row = bm * BM + ((m < 4) ? (ty * 4 + m) : (64 + ty * 4 + m - 4));
        float2 p0 = *(float2*)&acc[m][0];
        float2 p1 = *(float2*)&acc[m][1];
        float2 p2 = *(float2*)&acc[m][2];
        float2 p3 = *(float2*)&acc[m][3];
        float4 r0, r1;
        r0.x = fmaxf(p0.x + bv0.x, 0.f);
        r0.y = fmaxf(p0.y + bv0.y, 0.f);
        r0.z = fmaxf(p1.x + bv0.z, 0.f);
        r0.w = fmaxf(p1.y + bv0.w, 0.f);
        r1.x = fmaxf(p2.x + bv1.x, 0.f);
        r1.y = fmaxf(p2.y + bv1.y, 0.f);
        r1.z = fmaxf(p3.x + bv1.z, 0.f);
        r1.w = fmaxf(p3.y + bv1.w, 0.f);
        *(float4*)&C[(size_t)row * 256 + bn * BN + tx * 4] = r0;
        *(float4*)&C[(size_t)row * 256 + bn * BN + 64 + tx * 4] = r1;

        float s = r0.x * ws0.x + r0.y * ws0.y + r0.z * ws0.z + r0.w * ws0.w
                + r1.x * ws1.x + r1.y * ws1.y + r1.z * ws1.z + r1.w * ws1.w;
        float d = r0.x * wd0.x + r0.y * wd0.y + r0.z * wd0.z + r0.w * wd0.w
                + r1.x * wd1.x + r1.y * wd1.y + r1.z * wd1.z + r1.w * wd1.w;
#pragma unroll
        for (int o = 1; o < 16; o <<= 1) {   // reduce across tx (stays in 16-lane half)
            s += __shfl_xor_sync(0xffffffffu, s, o);
            d += __shfl_xor_sync(0xffffffffu, d, o);
        }
        if (tx == 0) {
            g_ps[bn * NN + row] = s;
            g_pd[bn * NN + row] = d;
        }
    }
}

// ---------------- edge scores from partials ----------------
__global__ void k_edge_score(const int* __restrict__ ei,
                             const float* __restrict__ bsc,
                             float* __restrict__ out) {
    int e = blockIdx.x * blockDim.x + threadIdx.x;
    if (e < ET) {
        int r = ei[e];
        int c = ei[ET + e];
        float ss = g_ps[r] + g_ps[NN + r];
        float sd = g_pd[c] + g_pd[NN + c];
        out[OFF_ES + e] = ss + sd + bsc[0];
    }
}

// ---------------- sort emit ----------------
__device__ __forceinline__ void sort_emit(int b, int idx_i, int i,
                                          const float* es, const int* ei,
                                          float* out) {
    int ge = b * EPER + idx_i;
    float s = es[ge];
    int r = ei[ge];
    int c = ei[ET + ge];
    if (i < NRES) {
        int p = b * NRES + i;
        out[OFF_CW + p] = s;
        g_cei[p] = r; g_cei[EC + p] = c;
        g_pres_c[r] = 1; g_pres_c[c] = 1;
    } else {
        int p = b * NRES + (i - NRES);
        out[OFF_FW + p] = -s;
        g_fei[p] = r; g_fei[EC + p] = c;
        g_pres_f[r] = 1; g_pres_f[c] = 1;
    }
}

// ---------------- sort: u64 packed keys, 64KB dynamic smem (measured 87us) ----------------
__global__ __launch_bounds__(1024) void k_sort64(const float* __restrict__ es,
                                                 const int* __restrict__ ei,
                                                 float* __restrict__ out) {
    extern __shared__ ull key[];
    const int b = blockIdx.x;
    const int tid = threadIdx.x;

    for (int i = tid; i < EPER; i += 1024) {
        unsigned u = __float_as_uint(es[b * EPER + i]);
        u = (u & 0x80000000u) ? ~u : (u | 0x80000000u);
        key[i] = ((ull)(~u) << 16) | (unsigned)i;
    }
    __syncthreads();

    for (int k = 2; k <= EPER; k <<= 1) {
        for (int j = k >> 1; j > 0; j >>= 1) {
#pragma unroll
            for (int q = 0; q < 4; q++) {
                int p = tid + q * 1024;
                int i = ((p & ~(j - 1)) << 1) | (p & (j - 1));
                int l = i | j;
                bool up = ((i & k) == 0);
                ull a = key[i], c = key[l];
                if ((a > c) == up) { key[i] = c; key[l] = a; }
            }
            __syncthreads();
        }
    }

    for (int i = tid; i < EPER; i += 1024) {
        int idx = (int)(key[i] & 0xFFFFu);
        sort_emit(b, idx, i, es, ei, out);
    }
}

// ---------------- FALLBACK sort: static 48KB (proven) ----------------
__global__ __launch_bounds__(1024) void k_sort_static(const float* __restrict__ es,
                                                      const int* __restrict__ ei,
                                                      float* __restrict__ out) {
    __shared__ unsigned int   kh[EPER];
    __shared__ unsigned short kl[EPER];
    const int b = blockIdx.x;
    const int tid = threadIdx.x;

    for (int i = tid; i < EPER; i += 1024) {
        unsigned u = __float_as_uint(es[b * EPER + i]);
        u = (u & 0x80000000u) ? ~u : (u | 0x80000000u);
        kh[i] = ~u;
        kl[i] = (unsigned short)i;
    }
    __syncthreads();

    for (int k = 2; k <= EPER; k <<= 1) {
        for (int j = k >> 1; j > 0; j >>= 1) {
#pragma unroll
            for (int q = 0; q < 4; q++) {
                int p = tid + q * 1024;
                int i = ((p & ~(j - 1)) << 1) | (p & (j - 1));
                int l = i | j;
                bool up = ((i & k) == 0);
                unsigned ah = kh[i], bh = kh[l];
                unsigned short al = kl[i], bl = kl[l];
                bool agtb = (ah > bh) || (ah == bh && al > bl);
                if (agtb == up) {
                    kh[i] = bh; kh[l] = ah;
                    kl[i] = bl; kl[l] = al;
                }
            }
            __syncthreads();
        }
    }

    for (int i = tid; i < EPER; i += 1024) {
        int idx = kl[i];
        sort_emit(b, idx, i, es, ei, out);
    }
}

// ---------------- relabel: compact + batch fill ----------------
__global__ __launch_bounds__(1024) void k_compact(const int* __restrict__ batch_in,
                                                  float* __restrict__ out) {
    __shared__ int part[1024];
    const int which = blockIdx.x;
    const int* pres = which ? g_pres_f : g_pres_c;
    int* rank = which ? g_rank_f : g_rank_c;
    int* list = which ? g_list_f : g_list_c;
    int* cnt = which ? &g_cnt_f : &g_cnt_c;
    float* out_b = out + (which ? OFF_FB : OFF_CB);

    const int t = threadIdx.x;
    const int base = t * 64;
    int s = 0;
    for (int i = 0; i < 64; i++) s += pres[base + i];
    part[t] = s;
    __syncthreads();
    for (int off = 1; off < 1024; off <<= 1) {
        int v = (t >= off) ? part[t - off] : 0;
        __syncthreads();
        part[t] += v;
        __syncthreads();
    }
    int total = part[1023];
    int run = part[t] - s;
    for (int i = 0; i < 64; i++) {
        int v = base + i;
        if (pres[v]) {
            rank[v] = run;
            list[run] = v;
            out_b[run] = (float)batch_in[v];
            run++;
        }
    }
    for (int i = 0; i < 64; i++) {
        int p = base + i;
        if (p >= total) out_b[p] = -1.0f;
    }
    if (t == 1023) *cnt = total;
}

// ---------------- fused emit: gather_x (bx < GX_BLK) + ei_rel (rest) ----------------
#define GX_BLK 16384   // NN*64/256
#define EIR_BLK 2048   // 2*EC/256

__global__ void k_emit(const float* __restrict__ h, float* __restrict__ out) {
    const int which = blockIdx.y;
    const int bx = blockIdx.x;
    if (bx < GX_BLK) {
        int gid = bx * 256 + threadIdx.x;
        int row = gid >> 6;
        int c = gid & 63;
        int cnt = which ? g_cnt_f : g_cnt_c;
        float4 v;
        if (row < cnt) {
            int src = which ? g_list_f[row] : g_list_c[row];
            v = ((const float4*)h)[(size_t)src * 64 + c];
        } else {
            v = make_float4(0.f, 0.f, 0.f, 0.f);
        }
        float* outx = out + (which ? OFF_FX : OFF_CX);
        ((float4*)outx)[gid] = v;
    } else {
        int k = (bx - GX_BLK) * 256 + threadIdx.x;
        const int* eib = which ? g_fei : g_cei;
        const int* rank = which ? g_rank_f : g_rank_c;
        float* dst = out + (which ? OFF_FEI : OFF_CEI);
        dst[k] = (float)rank[eib[k]];
    }
}

// tail: restore zero-state invariant for next graph replay
__global__ void k_rezero() {
    int i = blockIdx.x * blockDim.x + threadIdx.x;
    if (i <= NN) g_deg[i] = 0;
    if (i < NN) { g_pres_c[i] = 0; g_pres_f[i] = 0; }
}

// ---------------- launch ----------------
extern "C" void kernel_launch(void* const* d_in, const int* in_sizes, int n_in,
                              void* d_out, int out_size) {
    (void)in_sizes; (void)n_in; (void)out_size;
    const float* x    = (const float*)d_in[0];
    const int*   ei   = (const int*)d_in[1];
    const int*   batch= (const int*)d_in[2];
    const float* W11  = (const float*)d_in[3];
    const float* b11  = (const float*)d_in[4];
    const float* W12  = (const float*)d_in[5];
    const float* b12  = (const float*)d_in[6];
    const float* W21  = (const float*)d_in[7];
    const float* b21  = (const float*)d_in[8];
    const float* W22  = (const float*)d_in[9];
    const float* b22  = (const float*)d_in[10];
    const float* wsc  = (const float*)d_in[11];
    const float* bsc  = (const float*)d_in[12];
    float* out = (float*)d_out;

    const int SMEM_SORT = EPER * (int)sizeof(ull);   // 65536
    bool use64 = (cudaFuncSetAttribute(k_sort64,
                    cudaFuncAttributeMaxDynamicSharedMemorySize,
                    SMEM_SORT) == cudaSuccess);

    dim3 ggrid(NN / BM, HIDD / BN);   // (512, 2)

    k_count_deg<<<ET / 256, 256>>>(ei);                      // 0
    k_scan_deg<<<1, 1024>>>();                               // 1
    k_fill_csr<<<ET / 256, 256>>>(ei);                       // 2

    k_agg<<<NN / 2, 128>>>(x, g_t);                          // 3
    k_gemm_bias_relu<<<ggrid, 256>>>(g_t, W11, b11, g_u);    // 4
    k_gemm_bias_relu<<<ggrid, 256>>>(g_u, W12, b12, g_h);    // 5

    k_agg<<<NN / 2, 128>>>(g_h, g_t);                        // 6
    k_gemm_bias_relu<<<ggrid, 256>>>(g_t, W21, b21, g_u);    // 7
    k_gemm_score<<<ggrid, 256>>>(g_u, W22, b22, g_h, wsc);   // 8 (fused score)

    k_edge_score<<<ET / 256, 256>>>(ei, bsc, out);           // 9

    if (use64) {
        k_sort64<<<BB, 1024, SMEM_SORT>>>(out + OFF_ES, ei, out);   // 10
    } else {
        k_sort_static<<<BB, 1024>>>(out + OFF_ES, ei, out);         // 10
    }

    k_compact<<<2, 1024>>>(batch, out);                      // 11
    k_emit<<<dim3(GX_BLK + EIR_BLK, 2), 256>>>(g_h, out);    // 12

    k_rezero<<<(NN + 256) / 256, 256>>>();                   // 13
}